// round 1
// baseline (speedup 1.0000x reference)
#include <cuda_runtime.h>
#include <cuda_fp16.h>
#include <cstdint>

// Problem shape (fixed)
#define B_  64
#define N_  2048
#define I_  16
#define J_  32
#define K_  32
#define JK_ 1024

// Scratch: u_hat stored fp16 as [b][n][jk], jk = j*32+k  (256 MB)
__device__ __half g_uhat[(size_t)B_ * N_ * JK_];
__device__ float  g_s[B_ * JK_];   // routing-weighted sum s[b][j][k]
__device__ float  g_V[B_ * JK_];   // accumulated squash outputs (V_t)

// ---------------- packed fp32x2 helpers (sm_100+) ----------------
static __device__ __forceinline__ unsigned long long fma2(
    unsigned long long a, unsigned long long b, unsigned long long c) {
    unsigned long long d;
    asm("fma.rn.f32x2 %0, %1, %2, %3;" : "=l"(d) : "l"(a), "l"(b), "l"(c));
    return d;
}
static __device__ __forceinline__ float2 ull2f2(unsigned long long v) {
    float2 f;
    asm("mov.b64 {%0, %1}, %2;" : "=f"(f.x), "=f"(f.y) : "l"(v));
    return f;
}

// ---------------- init: zero s and V ----------------
__global__ void __launch_bounds__(1024) k_init() {
    int idx = blockIdx.x * 1024 + threadIdx.x;   // grid 64 -> exactly 65536
    g_s[idx] = 0.0f;
    g_V[idx] = 0.0f;
}

// ---------------- u_hat generation ----------------
// CTA = (n, jk-half). Covers all 64 b x 512 jk for one n.
// u_hat[b,n,jk] = sum_i inp[b,n,i] * W[j,n,k,i]
// fp32 compute via packed f32x2 FMA (inputs duplicated into both lanes,
// W provides two adjacent jk values per packed operand).
__global__ void __launch_bounds__(512) k_uhat(const float* __restrict__ inp,
                                              const float* __restrict__ W) {
    __shared__ float  Ws[16 * 512];    // [i][jk_local]  32 KB
    __shared__ float2 Id[16 * 64];     // [i][b] duplicated inputs  8 KB

    const int n   = blockIdx.x;        // 0..2047
    const int jkh = blockIdx.y;        // 0..1 (which 512-wide jk half)
    const int tid = threadIdx.x;       // 0..511

    // Stage W slice, transposed to i-major. Thread handles jk row = tid.
    {
        int jkg = jkh * 512 + tid;
        int j = jkg >> 5, k = jkg & 31;
        const float4* wsrc = reinterpret_cast<const float4*>(
            W + ((size_t)j * N_ + n) * (K_ * I_) + (size_t)k * I_);
        float4 r0 = wsrc[0], r1 = wsrc[1], r2 = wsrc[2], r3 = wsrc[3];
        Ws[0 * 512 + tid] = r0.x;  Ws[1 * 512 + tid] = r0.y;
        Ws[2 * 512 + tid] = r0.z;  Ws[3 * 512 + tid] = r0.w;
        Ws[4 * 512 + tid] = r1.x;  Ws[5 * 512 + tid] = r1.y;
        Ws[6 * 512 + tid] = r1.z;  Ws[7 * 512 + tid] = r1.w;
        Ws[8 * 512 + tid] = r2.x;  Ws[9 * 512 + tid] = r2.y;
        Ws[10 * 512 + tid] = r2.z; Ws[11 * 512 + tid] = r2.w;
        Ws[12 * 512 + tid] = r3.x; Ws[13 * 512 + tid] = r3.y;
        Ws[14 * 512 + tid] = r3.z; Ws[15 * 512 + tid] = r3.w;
    }
    // Stage duplicated inputs: Id[i][b] = (inp[b,n,i], inp[b,n,i])
    #pragma unroll
    for (int e = tid; e < 1024; e += 512) {
        int bl = e >> 4, i = e & 15;
        float v = inp[((size_t)bl * N_ + n) * I_ + i];
        Id[i * 64 + bl] = make_float2(v, v);
    }
    __syncthreads();

    // Thread tile: 4 consecutive jk x 16 b.
    const int jkq   = tid & 127;       // jk group (4 jk each)
    const int bbase = (tid >> 7) * 16; // 0,16,32,48

    unsigned long long acc[16][2];
    #pragma unroll
    for (int t = 0; t < 16; t++) { acc[t][0] = 0ull; acc[t][1] = 0ull; }

    #pragma unroll
    for (int i = 0; i < 16; i++) {
        const ulonglong2* IdU = reinterpret_cast<const ulonglong2*>(Id + i * 64 + bbase);
        ulonglong2 w = *reinterpret_cast<const ulonglong2*>(Ws + i * 512 + jkq * 4);
        #pragma unroll
        for (int q = 0; q < 8; q++) {
            ulonglong2 a = IdU[q];                       // 2 b's, duplicated
            acc[2 * q + 0][0] = fma2(a.x, w.x, acc[2 * q + 0][0]);
            acc[2 * q + 0][1] = fma2(a.x, w.y, acc[2 * q + 0][1]);
            acc[2 * q + 1][0] = fma2(a.y, w.x, acc[2 * q + 1][0]);
            acc[2 * q + 1][1] = fma2(a.y, w.y, acc[2 * q + 1][1]);
        }
    }

    const int jkg = jkh * 512 + jkq * 4;
    #pragma unroll
    for (int bb = 0; bb < 16; bb++) {
        int b = bbase + bb;
        float2 p0 = ull2f2(acc[bb][0]);
        float2 p1 = ull2f2(acc[bb][1]);
        __half2 h0 = __floats2half2_rn(p0.x, p0.y);
        __half2 h1 = __floats2half2_rn(p1.x, p1.y);
        uint2 o;
        o.x = *reinterpret_cast<unsigned int*>(&h0);
        o.y = *reinterpret_cast<unsigned int*>(&h1);
        *reinterpret_cast<uint2*>(&g_uhat[((size_t)b * N_ + n) * JK_ + jkg]) = o;
    }
}

// ---------------- fused routing pass ----------------
// One pass over u_hat computes b = uhat.V, c = softmax_j(b), s += c*uhat.
// CTA = (n-chunk of 128, b). Warp handles 16 n; lane = j; lane holds
// uh[j][:], V[j][:], s-partial[j][:] in registers. Softmax over j is a
// warp shuffle reduction.
__global__ void k_route(int useV) {
    __shared__ float s_sm[32 * 33];    // padded: bank = (j+k)%32, conflict-free

    const int chunk = blockIdx.x;      // 0..15
    const int b     = blockIdx.y;      // 0..63
    const int tid   = threadIdx.x;     // 256
    const int warp  = tid >> 5;
    const int lane  = tid & 31;        // = j

    for (int t = tid; t < 32 * 33; t += 256) s_sm[t] = 0.0f;

    float v[32];
    if (useV) {
        const float4* vp = reinterpret_cast<const float4*>(g_V + (size_t)b * JK_ + lane * 32);
        #pragma unroll
        for (int q = 0; q < 8; q++) {
            float4 f = vp[q];
            v[4 * q] = f.x; v[4 * q + 1] = f.y; v[4 * q + 2] = f.z; v[4 * q + 3] = f.w;
        }
    }
    float sacc[32];
    #pragma unroll
    for (int k = 0; k < 32; k++) sacc[k] = 0.0f;

    __syncthreads();

    for (int t = 0; t < 16; t++) {
        int n = chunk * 128 + warp * 16 + t;
        const uint4* up = reinterpret_cast<const uint4*>(
            &g_uhat[((size_t)b * N_ + n) * JK_ + lane * 32]);
        float uf[32];
        #pragma unroll
        for (int q = 0; q < 4; q++) {
            uint4 u = up[q];
            float2 f0 = __half22float2(*reinterpret_cast<__half2*>(&u.x));
            float2 f1 = __half22float2(*reinterpret_cast<__half2*>(&u.y));
            float2 f2 = __half22float2(*reinterpret_cast<__half2*>(&u.z));
            float2 f3 = __half22float2(*reinterpret_cast<__half2*>(&u.w));
            uf[8 * q + 0] = f0.x; uf[8 * q + 1] = f0.y;
            uf[8 * q + 2] = f1.x; uf[8 * q + 3] = f1.y;
            uf[8 * q + 4] = f2.x; uf[8 * q + 5] = f2.y;
            uf[8 * q + 6] = f3.x; uf[8 * q + 7] = f3.y;
        }
        float c;
        if (useV) {
            float bj = 0.0f;
            #pragma unroll
            for (int k = 0; k < 32; k++) bj = fmaf(uf[k], v[k], bj);
            float m = bj;
            #pragma unroll
            for (int o = 16; o; o >>= 1) m = fmaxf(m, __shfl_xor_sync(0xffffffffu, m, o));
            float e = __expf(bj - m);
            float ssum = e;
            #pragma unroll
            for (int o = 16; o; o >>= 1) ssum += __shfl_xor_sync(0xffffffffu, ssum, o);
            c = e / ssum;
        } else {
            c = 1.0f / 32.0f;          // softmax of zeros
        }
        #pragma unroll
        for (int k = 0; k < 32; k++) sacc[k] = fmaf(c, uf[k], sacc[k]);
    }

    #pragma unroll
    for (int k = 0; k < 32; k++) atomicAdd(&s_sm[lane * 33 + k], sacc[k]);
    __syncthreads();
    for (int t = tid; t < 1024; t += 256)
        atomicAdd(&g_s[b * JK_ + t], s_sm[(t >> 5) * 33 + (t & 31)]);
}

// ---------------- squash + V update / final output ----------------
__global__ void __launch_bounds__(1024) k_squash(float* __restrict__ out, int final_iter) {
    const int b   = blockIdx.x;
    const int tid = threadIdx.x;       // warp = j, lane = k
    float sv = g_s[b * JK_ + tid];
    float sq = sv * sv;
    #pragma unroll
    for (int o = 16; o; o >>= 1) sq += __shfl_xor_sync(0xffffffffu, sq, o);
    float scale = sq / ((1.0f + sq) * sqrtf(sq + 1e-7f));
    float o = scale * sv;
    if (final_iter) {
        out[b * JK_ + tid] = o;
    } else {
        g_V[b * JK_ + tid] += o;       // V_{t+1} = sum of outputs so far
        g_s[b * JK_ + tid]  = 0.0f;    // clear accumulator for next pass
    }
}

extern "C" void kernel_launch(void* const* d_in, const int* in_sizes, int n_in,
                              void* d_out, int out_size) {
    const float* inp = (const float*)d_in[0];   // [64, 2048, 16]
    const float* W   = (const float*)d_in[1];   // [32, 2048, 32, 16]
    float* out = (float*)d_out;                 // [64, 32, 32]

    k_init<<<64, 1024>>>();
    k_uhat<<<dim3(2048, 2), 512>>>(inp, W);

    // iter 0: c = 1/32 (softmax of zeros)
    k_route<<<dim3(16, 64), 256>>>(0);
    k_squash<<<64, 1024>>>(out, 0);
    // iter 1: b1 = uhat . out0
    k_route<<<dim3(16, 64), 256>>>(1);
    k_squash<<<64, 1024>>>(out, 0);
    // iter 2: b2 = uhat . (out0 + out1), final
    k_route<<<dim3(16, 64), 256>>>(1);
    k_squash<<<64, 1024>>>(out, 1);
}

// round 2
// speedup vs baseline: 1.1387x; 1.1387x over previous
#include <cuda_runtime.h>
#include <cuda_fp16.h>
#include <cstdint>

#define B_  64
#define N_  2048
#define I_  16
#define J_  32
#define K_  32
#define JK_ 1024

typedef unsigned long long ull;

// Scratch: u_hat fp16 [b][n][jk] (256 MB), s and V accumulators
__device__ __half g_uhat[(size_t)B_ * N_ * JK_];
__device__ float  g_s[B_ * JK_];
__device__ float  g_V[B_ * JK_];

// ---------------- packed fp32x2 helpers (sm_100+) ----------------
static __device__ __forceinline__ ull fma2(ull a, ull b, ull c) {
    ull d;
    asm("fma.rn.f32x2 %0, %1, %2, %3;" : "=l"(d) : "l"(a), "l"(b), "l"(c));
    return d;
}
static __device__ __forceinline__ float2 ull2f2(ull v) {
    float2 f;
    asm("mov.b64 {%0, %1}, %2;" : "=f"(f.x), "=f"(f.y) : "l"(v));
    return f;
}
static __device__ __forceinline__ ull packf2(float x, float y) {
    ull r;
    asm("mov.b64 %0, {%1, %2};" : "=l"(r) : "f"(x), "f"(y));
    return r;
}
static __device__ __forceinline__ ull dupf(float x) {
    ull r;
    asm("mov.b64 %0, {%1, %1};" : "=l"(r) : "f"(x));
    return r;
}
// half2 bits -> packed float2 (as ull)
static __device__ __forceinline__ ull h2f2(unsigned int h) {
    __half2 hh = *reinterpret_cast<__half2*>(&h);
    float2 f = __half22float2(hh);
    return packf2(f.x, f.y);
}

// ---------------- init ----------------
__global__ void __launch_bounds__(1024) k_init() {
    int idx = blockIdx.x * 1024 + threadIdx.x;   // grid 64 -> 65536
    g_s[idx] = 0.0f;
    g_V[idx] = 0.0f;
}

// ---------------- u_hat generation ----------------
// CTA = (n, jk-half). Thread tile: 4 jk x 16 b (8 b-pairs).
// W duplicated in registers; inputs packed (b,b+1) pairs from smem broadcast.
__global__ void __launch_bounds__(512, 1) k_uhat(const float* __restrict__ inp,
                                                 const float* __restrict__ W) {
    __shared__ float Ws[16 * 512];   // [i][jk_local]  32 KB
    __shared__ float Is[16 * 64];    // [i][b] non-duplicated  4 KB

    const int n   = blockIdx.x;      // 0..2047
    const int jkh = blockIdx.y;      // 0..1
    const int tid = threadIdx.x;     // 0..511

    // Stage W slice, i-major.
    {
        int jkg = jkh * 512 + tid;
        int j = jkg >> 5, k = jkg & 31;
        const float4* wsrc = reinterpret_cast<const float4*>(
            W + ((size_t)j * N_ + n) * (K_ * I_) + (size_t)k * I_);
        float4 r0 = wsrc[0], r1 = wsrc[1], r2 = wsrc[2], r3 = wsrc[3];
        Ws[0 * 512 + tid] = r0.x;  Ws[1 * 512 + tid] = r0.y;
        Ws[2 * 512 + tid] = r0.z;  Ws[3 * 512 + tid] = r0.w;
        Ws[4 * 512 + tid] = r1.x;  Ws[5 * 512 + tid] = r1.y;
        Ws[6 * 512 + tid] = r1.z;  Ws[7 * 512 + tid] = r1.w;
        Ws[8 * 512 + tid] = r2.x;  Ws[9 * 512 + tid] = r2.y;
        Ws[10 * 512 + tid] = r2.z; Ws[11 * 512 + tid] = r2.w;
        Ws[12 * 512 + tid] = r3.x; Ws[13 * 512 + tid] = r3.y;
        Ws[14 * 512 + tid] = r3.z; Ws[15 * 512 + tid] = r3.w;
    }
    // Stage inputs [i][b] (not duplicated).
    #pragma unroll
    for (int e = tid; e < 1024; e += 512) {
        int bl = e >> 4, i = e & 15;
        Is[i * 64 + bl] = inp[((size_t)bl * N_ + n) * I_ + i];
    }
    __syncthreads();

    const int jkq   = tid & 127;        // 4-jk group
    const int bbase = (tid >> 7) * 16;  // 0,16,32,48

    ull acc[4][8];
    #pragma unroll
    for (int a = 0; a < 4; a++)
        #pragma unroll
        for (int p = 0; p < 8; p++) acc[a][p] = 0ull;

    #pragma unroll
    for (int i = 0; i < 16; i++) {
        float4 w = *reinterpret_cast<const float4*>(Ws + i * 512 + jkq * 4);
        ull wd0 = dupf(w.x), wd1 = dupf(w.y), wd2 = dupf(w.z), wd3 = dupf(w.w);
        const ulonglong2* ip = reinterpret_cast<const ulonglong2*>(Is + i * 64 + bbase);
        #pragma unroll
        for (int q = 0; q < 4; q++) {           // broadcast LDS.128: 2 b-pairs each
            ulonglong2 in2 = ip[q];
            acc[0][2 * q + 0] = fma2(wd0, in2.x, acc[0][2 * q + 0]);
            acc[1][2 * q + 0] = fma2(wd1, in2.x, acc[1][2 * q + 0]);
            acc[2][2 * q + 0] = fma2(wd2, in2.x, acc[2][2 * q + 0]);
            acc[3][2 * q + 0] = fma2(wd3, in2.x, acc[3][2 * q + 0]);
            acc[0][2 * q + 1] = fma2(wd0, in2.y, acc[0][2 * q + 1]);
            acc[1][2 * q + 1] = fma2(wd1, in2.y, acc[1][2 * q + 1]);
            acc[2][2 * q + 1] = fma2(wd2, in2.y, acc[2][2 * q + 1]);
            acc[3][2 * q + 1] = fma2(wd3, in2.y, acc[3][2 * q + 1]);
        }
    }

    const int jkg = jkh * 512 + jkq * 4;
    #pragma unroll
    for (int p = 0; p < 8; p++) {
        float2 f0 = ull2f2(acc[0][p]);
        float2 f1 = ull2f2(acc[1][p]);
        float2 f2 = ull2f2(acc[2][p]);
        float2 f3 = ull2f2(acc[3][p]);
        int b0 = bbase + 2 * p;
        __half2 x0 = __floats2half2_rn(f0.x, f1.x);
        __half2 x1 = __floats2half2_rn(f2.x, f3.x);
        __half2 y0 = __floats2half2_rn(f0.y, f1.y);
        __half2 y1 = __floats2half2_rn(f2.y, f3.y);
        uint2 ox, oy;
        ox.x = *reinterpret_cast<unsigned int*>(&x0);
        ox.y = *reinterpret_cast<unsigned int*>(&x1);
        oy.x = *reinterpret_cast<unsigned int*>(&y0);
        oy.y = *reinterpret_cast<unsigned int*>(&y1);
        *reinterpret_cast<uint2*>(&g_uhat[((size_t)b0 * N_ + n) * JK_ + jkg]) = ox;
        *reinterpret_cast<uint2*>(&g_uhat[((size_t)(b0 + 1) * N_ + n) * JK_ + jkg]) = oy;
    }
}

// ---------------- fused routing pass ----------------
// CTA = (n-chunk of 128, b). Warp handles 16 n; lane = j.
// All arithmetic on packed f32x2 pairs; softmax without max-subtraction.
__global__ void __launch_bounds__(256, 2) k_route(int useV) {
    __shared__ float s_sm[32 * 33];

    const int chunk = blockIdx.x;   // 0..15
    const int b     = blockIdx.y;   // 0..63
    const int tid   = threadIdx.x;  // 256
    const int warp  = tid >> 5;
    const int lane  = tid & 31;     // = j

    for (int t = tid; t < 32 * 33; t += 256) s_sm[t] = 0.0f;

    ull v2[16];
    if (useV) {
        const float4* vp = reinterpret_cast<const float4*>(g_V + (size_t)b * JK_ + lane * 32);
        #pragma unroll
        for (int q = 0; q < 8; q++) {
            float4 f = vp[q];
            v2[2 * q]     = packf2(f.x, f.y);
            v2[2 * q + 1] = packf2(f.z, f.w);
        }
    }
    ull sacc[16];
    #pragma unroll
    for (int q = 0; q < 16; q++) sacc[q] = 0ull;

    __syncthreads();

    const __half* base = g_uhat + ((size_t)b * N_ + (size_t)(chunk * 128 + warp * 16)) * JK_
                         + lane * 32;
    for (int t = 0; t < 16; t++) {
        const uint4* up = reinterpret_cast<const uint4*>(base + (size_t)t * JK_);
        ull uf[16];
        #pragma unroll
        for (int q = 0; q < 4; q++) {
            uint4 u = up[q];
            uf[4 * q + 0] = h2f2(u.x);
            uf[4 * q + 1] = h2f2(u.y);
            uf[4 * q + 2] = h2f2(u.z);
            uf[4 * q + 3] = h2f2(u.w);
        }
        float c;
        if (useV) {
            ull d = 0ull;
            #pragma unroll
            for (int q = 0; q < 16; q++) d = fma2(uf[q], v2[q], d);
            float2 df = ull2f2(d);
            float bj = df.x + df.y;
            float e = __expf(bj);          // logits bounded; no max needed
            float ssum = e;
            #pragma unroll
            for (int o = 16; o; o >>= 1) ssum += __shfl_xor_sync(0xffffffffu, ssum, o);
            c = e / ssum;
        } else {
            c = 0.03125f;                   // softmax of zeros
        }
        ull c2 = dupf(c);
        #pragma unroll
        for (int q = 0; q < 16; q++) sacc[q] = fma2(c2, uf[q], sacc[q]);
    }

    #pragma unroll
    for (int q = 0; q < 16; q++) {
        float2 f = ull2f2(sacc[q]);
        atomicAdd(&s_sm[lane * 33 + 2 * q],     f.x);
        atomicAdd(&s_sm[lane * 33 + 2 * q + 1], f.y);
    }
    __syncthreads();
    for (int t = tid; t < 1024; t += 256)
        atomicAdd(&g_s[b * JK_ + t], s_sm[(t >> 5) * 33 + (t & 31)]);
}

// ---------------- squash ----------------
__global__ void __launch_bounds__(1024) k_squash(float* __restrict__ out, int final_iter) {
    const int b   = blockIdx.x;
    const int tid = threadIdx.x;    // warp = j, lane = k
    float sv = g_s[b * JK_ + tid];
    float sq = sv * sv;
    #pragma unroll
    for (int o = 16; o; o >>= 1) sq += __shfl_xor_sync(0xffffffffu, sq, o);
    float scale = sq / ((1.0f + sq) * sqrtf(sq + 1e-7f));
    float o = scale * sv;
    if (final_iter) {
        out[b * JK_ + tid] = o;
    } else {
        g_V[b * JK_ + tid] += o;
        g_s[b * JK_ + tid]  = 0.0f;
    }
}

extern "C" void kernel_launch(void* const* d_in, const int* in_sizes, int n_in,
                              void* d_out, int out_size) {
    const float* inp = (const float*)d_in[0];   // [64, 2048, 16]
    const float* W   = (const float*)d_in[1];   // [32, 2048, 32, 16]
    float* out = (float*)d_out;                 // [64, 32, 32]

    k_init<<<64, 1024>>>();
    k_uhat<<<dim3(2048, 2), 512>>>(inp, W);

    k_route<<<dim3(16, 64), 256>>>(0);
    k_squash<<<64, 1024>>>(out, 0);
    k_route<<<dim3(16, 64), 256>>>(1);
    k_squash<<<64, 1024>>>(out, 0);
    k_route<<<dim3(16, 64), 256>>>(1);
    k_squash<<<64, 1024>>>(out, 1);
}

// round 3
// speedup vs baseline: 1.2474x; 1.0955x over previous
#include <cuda_runtime.h>
#include <cuda_fp16.h>
#include <cstdint>

#define B_  64
#define N_  2048
#define I_  16
#define JK_ 1024

typedef unsigned long long ull;

// Scratch: u_hat fp16 [b][n][jk] (256 MB), s and V accumulators
__device__ __half g_uhat[(size_t)B_ * N_ * JK_];
__device__ float  g_s[B_ * JK_];
__device__ float  g_V[B_ * JK_];

// ---------------- packed fp32x2 helpers (sm_100+) ----------------
static __device__ __forceinline__ ull fma2(ull a, ull b, ull c) {
    ull d;
    asm("fma.rn.f32x2 %0, %1, %2, %3;" : "=l"(d) : "l"(a), "l"(b), "l"(c));
    return d;
}
static __device__ __forceinline__ float2 ull2f2(ull v) {
    float2 f;
    asm("mov.b64 {%0, %1}, %2;" : "=f"(f.x), "=f"(f.y) : "l"(v));
    return f;
}
static __device__ __forceinline__ ull packf2(float x, float y) {
    ull r;
    asm("mov.b64 %0, {%1, %2};" : "=l"(r) : "f"(x), "f"(y));
    return r;
}
static __device__ __forceinline__ ull dupf(float x) {
    ull r;
    asm("mov.b64 %0, {%1, %1};" : "=l"(r) : "f"(x));
    return r;
}
static __device__ __forceinline__ ull h2f2(unsigned int h) {
    __half2 hh = *reinterpret_cast<__half2*>(&h);
    float2 f = __half22float2(hh);
    return packf2(f.x, f.y);
}
static __device__ __forceinline__ void red4(float* p, float4 v) {
    asm volatile("red.global.add.v4.f32 [%0], {%1,%2,%3,%4};"
                 :: "l"(p), "f"(v.x), "f"(v.y), "f"(v.z), "f"(v.w) : "memory");
}

// ---------------- pads (profiling alignment) + init ----------------
__global__ void k_pad() {}

__global__ void __launch_bounds__(1024) k_init() {
    int idx = blockIdx.x * 1024 + threadIdx.x;   // grid 64 -> 65536
    g_s[idx] = 0.0f;
    g_V[idx] = 0.0f;
}

// ---------------- fused u_hat generation + iteration-0 s ----------------
// Persistent: grid 296 = 148 n-strips x 2 jk-halves. Each CTA loops its n's
// with double-buffered staging, writes u_hat fp16, and accumulates
// s0 = (1/32) * sum_n u_hat (fp32, pre-rounding) in smem, flushed by atomics.
__global__ void __launch_bounds__(512, 1) k_uhat(const float* __restrict__ inp,
                                                 const float* __restrict__ W) {
    extern __shared__ float sm[];
    float* S0  = sm;                 // 64b x 512jk = 32768 floats (128 KB)
    float* Wb0 = sm + 32768;         // 16i x 512jk
    float* Wb1 = sm + 40960;
    float* Xs0 = sm + 49152;         // 16i x 64b
    float* Xs1 = sm + 50176;         // total 51200 floats = 200 KB

    const int tid = threadIdx.x;
    const int jkh = blockIdx.x & 1;
    const int idx = blockIdx.x >> 1;   // 0..147

    for (int t = tid; t < 32768; t += 512) S0[t] = 0.0f;

    // staging source addresses
    const int jkg = jkh * 512 + tid;
    const int wj = jkg >> 5, wk = jkg & 31;
    const float* wbase = W + (size_t)wj * N_ * 512 + wk * 16;   // + n*512
    const int xb = tid >> 3, xi = (tid & 7) * 2;
    const float* xbase = inp + (size_t)xb * N_ * 16 + xi;       // + n*16

    const int jkq = tid & 63;      // jk group: jk = jkq*4 (+0..3) and 256+jkq*4
    const int bq  = tid >> 6;      // 8-b group

    const int total = (N_ - idx + 147) / 148;

    float4 wr0, wr1, wr2, wr3; float2 xr;
    {   // prologue: load + stage tile 0 into buffer 0
        const float4* ws = reinterpret_cast<const float4*>(wbase + (size_t)idx * 512);
        wr0 = ws[0]; wr1 = ws[1]; wr2 = ws[2]; wr3 = ws[3];
        xr = *reinterpret_cast<const float2*>(xbase + (size_t)idx * 16);
        Wb0[0*512+tid]=wr0.x;  Wb0[1*512+tid]=wr0.y;  Wb0[2*512+tid]=wr0.z;  Wb0[3*512+tid]=wr0.w;
        Wb0[4*512+tid]=wr1.x;  Wb0[5*512+tid]=wr1.y;  Wb0[6*512+tid]=wr1.z;  Wb0[7*512+tid]=wr1.w;
        Wb0[8*512+tid]=wr2.x;  Wb0[9*512+tid]=wr2.y;  Wb0[10*512+tid]=wr2.z; Wb0[11*512+tid]=wr2.w;
        Wb0[12*512+tid]=wr3.x; Wb0[13*512+tid]=wr3.y; Wb0[14*512+tid]=wr3.z; Wb0[15*512+tid]=wr3.w;
        Xs0[xi * 64 + xb] = xr.x;
        Xs0[(xi + 1) * 64 + xb] = xr.y;
    }

    const ull c2 = dupf(0.03125f);

    for (int t = 0; t < total; t++) {
        __syncthreads();
        const int ncur = idx + t * 148;
        const bool more = (t + 1 < total);
        if (more) {   // prefetch next tile into registers (latency hidden by compute)
            const int nn = ncur + 148;
            const float4* ws = reinterpret_cast<const float4*>(wbase + (size_t)nn * 512);
            wr0 = ws[0]; wr1 = ws[1]; wr2 = ws[2]; wr3 = ws[3];
            xr = *reinterpret_cast<const float2*>(xbase + (size_t)nn * 16);
        }
        const float* Wc = (t & 1) ? Wb1 : Wb0;
        const float* Xc = (t & 1) ? Xs1 : Xs0;

        // acc[m][p]: m = jk slot (0..3 -> jkq*4+m, 4..7 -> 256+jkq*4+m-4),
        //            p = b-pair (b = bq*8 + 2p, 2p+1) packed in f32x2 lanes
        ull acc[8][4];
        #pragma unroll
        for (int m = 0; m < 8; m++)
            #pragma unroll
            for (int p = 0; p < 4; p++) acc[m][p] = 0ull;

        #pragma unroll
        for (int i = 0; i < 16; i++) {
            float4 wa = *reinterpret_cast<const float4*>(Wc + i * 512 + jkq * 4);
            float4 wb = *reinterpret_cast<const float4*>(Wc + i * 512 + 256 + jkq * 4);
            ull wd0 = dupf(wa.x), wd1 = dupf(wa.y), wd2 = dupf(wa.z), wd3 = dupf(wa.w);
            ull wd4 = dupf(wb.x), wd5 = dupf(wb.y), wd6 = dupf(wb.z), wd7 = dupf(wb.w);
            ulonglong2 xu0 = *reinterpret_cast<const ulonglong2*>(Xc + i * 64 + bq * 8);
            ulonglong2 xu1 = *reinterpret_cast<const ulonglong2*>(Xc + i * 64 + bq * 8 + 4);
            ull xp0 = xu0.x, xp1 = xu0.y, xp2 = xu1.x, xp3 = xu1.y;
            acc[0][0]=fma2(wd0,xp0,acc[0][0]); acc[0][1]=fma2(wd0,xp1,acc[0][1]);
            acc[0][2]=fma2(wd0,xp2,acc[0][2]); acc[0][3]=fma2(wd0,xp3,acc[0][3]);
            acc[1][0]=fma2(wd1,xp0,acc[1][0]); acc[1][1]=fma2(wd1,xp1,acc[1][1]);
            acc[1][2]=fma2(wd1,xp2,acc[1][2]); acc[1][3]=fma2(wd1,xp3,acc[1][3]);
            acc[2][0]=fma2(wd2,xp0,acc[2][0]); acc[2][1]=fma2(wd2,xp1,acc[2][1]);
            acc[2][2]=fma2(wd2,xp2,acc[2][2]); acc[2][3]=fma2(wd2,xp3,acc[2][3]);
            acc[3][0]=fma2(wd3,xp0,acc[3][0]); acc[3][1]=fma2(wd3,xp1,acc[3][1]);
            acc[3][2]=fma2(wd3,xp2,acc[3][2]); acc[3][3]=fma2(wd3,xp3,acc[3][3]);
            acc[4][0]=fma2(wd4,xp0,acc[4][0]); acc[4][1]=fma2(wd4,xp1,acc[4][1]);
            acc[4][2]=fma2(wd4,xp2,acc[4][2]); acc[4][3]=fma2(wd4,xp3,acc[4][3]);
            acc[5][0]=fma2(wd5,xp0,acc[5][0]); acc[5][1]=fma2(wd5,xp1,acc[5][1]);
            acc[5][2]=fma2(wd5,xp2,acc[5][2]); acc[5][3]=fma2(wd5,xp3,acc[5][3]);
            acc[6][0]=fma2(wd6,xp0,acc[6][0]); acc[6][1]=fma2(wd6,xp1,acc[6][1]);
            acc[6][2]=fma2(wd6,xp2,acc[6][2]); acc[6][3]=fma2(wd6,xp3,acc[6][3]);
            acc[7][0]=fma2(wd7,xp0,acc[7][0]); acc[7][1]=fma2(wd7,xp1,acc[7][1]);
            acc[7][2]=fma2(wd7,xp2,acc[7][2]); acc[7][3]=fma2(wd7,xp3,acc[7][3]);
        }

        if (more) {   // stage prefetched tile into other buffer
            float* Wn = (t & 1) ? Wb0 : Wb1;
            float* Xn = (t & 1) ? Xs0 : Xs1;
            Wn[0*512+tid]=wr0.x;  Wn[1*512+tid]=wr0.y;  Wn[2*512+tid]=wr0.z;  Wn[3*512+tid]=wr0.w;
            Wn[4*512+tid]=wr1.x;  Wn[5*512+tid]=wr1.y;  Wn[6*512+tid]=wr1.z;  Wn[7*512+tid]=wr1.w;
            Wn[8*512+tid]=wr2.x;  Wn[9*512+tid]=wr2.y;  Wn[10*512+tid]=wr2.z; Wn[11*512+tid]=wr2.w;
            Wn[12*512+tid]=wr3.x; Wn[13*512+tid]=wr3.y; Wn[14*512+tid]=wr3.z; Wn[15*512+tid]=wr3.w;
            Xn[xi * 64 + xb] = xr.x;
            Xn[(xi + 1) * 64 + xb] = xr.y;
        }

        // epilogue: S0 += acc/32 (fp32), u_hat fp16 store
        #pragma unroll
        for (int p = 0; p < 4; p++) {
            float2 a0 = ull2f2(acc[0][p]), a1 = ull2f2(acc[1][p]);
            float2 a2 = ull2f2(acc[2][p]), a3 = ull2f2(acc[3][p]);
            float2 a4 = ull2f2(acc[4][p]), a5 = ull2f2(acc[5][p]);
            float2 a6 = ull2f2(acc[6][p]), a7 = ull2f2(acc[7][p]);
            #pragma unroll
            for (int e = 0; e < 2; e++) {
                const int bg = bq * 8 + 2 * p + e;
                float f0 = e ? a0.y : a0.x, f1 = e ? a1.y : a1.x;
                float f2 = e ? a2.y : a2.x, f3 = e ? a3.y : a3.x;
                float f4 = e ? a4.y : a4.x, f5 = e ? a5.y : a5.x;
                float f6 = e ? a6.y : a6.x, f7 = e ? a7.y : a7.x;

                float* sA = S0 + bg * 512 + jkq * 4;
                ulonglong2 oA = *reinterpret_cast<ulonglong2*>(sA);
                oA.x = fma2(packf2(f0, f1), c2, oA.x);
                oA.y = fma2(packf2(f2, f3), c2, oA.y);
                *reinterpret_cast<ulonglong2*>(sA) = oA;
                float* sB = S0 + bg * 512 + 256 + jkq * 4;
                ulonglong2 oB = *reinterpret_cast<ulonglong2*>(sB);
                oB.x = fma2(packf2(f4, f5), c2, oB.x);
                oB.y = fma2(packf2(f6, f7), c2, oB.y);
                *reinterpret_cast<ulonglong2*>(sB) = oB;

                __half2 hA0 = __floats2half2_rn(f0, f1), hA1 = __floats2half2_rn(f2, f3);
                __half2 hB0 = __floats2half2_rn(f4, f5), hB1 = __floats2half2_rn(f6, f7);
                __half* up = g_uhat + ((size_t)bg * N_ + ncur) * JK_ + jkh * 512;
                uint2 vA, vB;
                vA.x = *reinterpret_cast<unsigned int*>(&hA0);
                vA.y = *reinterpret_cast<unsigned int*>(&hA1);
                vB.x = *reinterpret_cast<unsigned int*>(&hB0);
                vB.y = *reinterpret_cast<unsigned int*>(&hB1);
                *reinterpret_cast<uint2*>(up + jkq * 4) = vA;
                *reinterpret_cast<uint2*>(up + 256 + jkq * 4) = vB;
            }
        }
    }

    __syncthreads();
    // flush S0 -> g_s with vector reductions
    for (int t2 = tid; t2 < 8192; t2 += 512) {
        int b = t2 >> 7;
        int c = (t2 & 127) * 4;
        float4 v = *reinterpret_cast<float4*>(S0 + b * 512 + c);
        red4(g_s + b * JK_ + jkh * 512 + c, v);
    }
}

// ---------------- fused routing pass (iterations 1,2) ----------------
__global__ void __launch_bounds__(256, 2) k_route(int useV) {
    __shared__ float s_sm[32 * 33];

    const int chunk = blockIdx.x;   // 0..15
    const int b     = blockIdx.y;   // 0..63
    const int tid   = threadIdx.x;  // 256
    const int warp  = tid >> 5;
    const int lane  = tid & 31;     // = j

    for (int t = tid; t < 32 * 33; t += 256) s_sm[t] = 0.0f;

    ull v2[16];
    if (useV) {
        const float4* vp = reinterpret_cast<const float4*>(g_V + (size_t)b * JK_ + lane * 32);
        #pragma unroll
        for (int q = 0; q < 8; q++) {
            float4 f = vp[q];
            v2[2 * q]     = packf2(f.x, f.y);
            v2[2 * q + 1] = packf2(f.z, f.w);
        }
    }
    ull sacc[16];
    #pragma unroll
    for (int q = 0; q < 16; q++) sacc[q] = 0ull;

    __syncthreads();

    const __half* base = g_uhat + ((size_t)b * N_ + (size_t)(chunk * 128 + warp * 16)) * JK_
                         + lane * 32;
    for (int t = 0; t < 16; t++) {
        const uint4* up = reinterpret_cast<const uint4*>(base + (size_t)t * JK_);
        ull uf[16];
        #pragma unroll
        for (int q = 0; q < 4; q++) {
            uint4 u = up[q];
            uf[4 * q + 0] = h2f2(u.x);
            uf[4 * q + 1] = h2f2(u.y);
            uf[4 * q + 2] = h2f2(u.z);
            uf[4 * q + 3] = h2f2(u.w);
        }
        float c;
        if (useV) {
            ull d = 0ull;
            #pragma unroll
            for (int q = 0; q < 16; q++) d = fma2(uf[q], v2[q], d);
            float2 df = ull2f2(d);
            float bj = df.x + df.y;
            float e = __expf(bj);          // logits bounded; no max needed
            float ssum = e;
            #pragma unroll
            for (int o = 16; o; o >>= 1) ssum += __shfl_xor_sync(0xffffffffu, ssum, o);
            c = e / ssum;
        } else {
            c = 0.03125f;
        }
        ull c2 = dupf(c);
        #pragma unroll
        for (int q = 0; q < 16; q++) sacc[q] = fma2(c2, uf[q], sacc[q]);
    }

    #pragma unroll
    for (int q = 0; q < 16; q++) {
        float2 f = ull2f2(sacc[q]);
        atomicAdd(&s_sm[lane * 33 + 2 * q],     f.x);
        atomicAdd(&s_sm[lane * 33 + 2 * q + 1], f.y);
    }
    __syncthreads();
    for (int t = tid; t < 1024; t += 256)
        atomicAdd(&g_s[b * JK_ + t], s_sm[(t >> 5) * 33 + (t & 31)]);
}

// ---------------- squash ----------------
__global__ void __launch_bounds__(1024) k_squash(float* __restrict__ out, int final_iter) {
    const int b   = blockIdx.x;
    const int tid = threadIdx.x;    // warp = j, lane = k
    float sv = g_s[b * JK_ + tid];
    float sq = sv * sv;
    #pragma unroll
    for (int o = 16; o; o >>= 1) sq += __shfl_xor_sync(0xffffffffu, sq, o);
    float scale = sq / ((1.0f + sq) * sqrtf(sq + 1e-7f));
    float o = scale * sv;
    if (final_iter) {
        out[b * JK_ + tid] = o;
    } else {
        g_V[b * JK_ + tid] += o;
        g_s[b * JK_ + tid]  = 0.0f;
    }
}

extern "C" void kernel_launch(void* const* d_in, const int* in_sizes, int n_in,
                              void* d_out, int out_size) {
    const float* inp = (const float*)d_in[0];   // [64, 2048, 16]
    const float* W   = (const float*)d_in[1];   // [32, 2048, 32, 16]
    float* out = (float*)d_out;                 // [64, 32, 32]

    cudaFuncSetAttribute(k_uhat, cudaFuncAttributeMaxDynamicSharedMemorySize, 204800);

    // 4 pads + init so ncu (-s 5 -c 1) captures k_uhat as launch #6
    k_pad<<<1, 32>>>();
    k_pad<<<1, 32>>>();
    k_pad<<<1, 32>>>();
    k_pad<<<1, 32>>>();
    k_init<<<64, 1024>>>();

    k_uhat<<<296, 512, 204800>>>(inp, W);       // u_hat + s0 fused

    k_squash<<<64, 1024>>>(out, 0);             // V0
    k_route<<<dim3(16, 64), 256>>>(1);          // s1
    k_squash<<<64, 1024>>>(out, 0);             // V0+V1
    k_route<<<dim3(16, 64), 256>>>(1);          // s2
    k_squash<<<64, 1024>>>(out, 1);             // final
}

// round 5
// speedup vs baseline: 1.2875x; 1.0322x over previous
#include <cuda_runtime.h>
#include <cuda_fp16.h>
#include <cstdint>

#define B_  64
#define N_  2048
#define I_  16
#define JK_ 1024

typedef unsigned long long ull;

// Scratch: u_hat fp16 [b][n][jk] (256 MB); three s buffers (iter 0,1,2)
__device__ __half g_uhat[(size_t)B_ * N_ * JK_];
__device__ float  g_sb[3][B_ * JK_];

// ---------------- packed fp32x2 helpers (sm_100+) ----------------
static __device__ __forceinline__ ull fma2(ull a, ull b, ull c) {
    ull d;
    asm("fma.rn.f32x2 %0, %1, %2, %3;" : "=l"(d) : "l"(a), "l"(b), "l"(c));
    return d;
}
static __device__ __forceinline__ float2 ull2f2(ull v) {
    float2 f;
    asm("mov.b64 {%0, %1}, %2;" : "=f"(f.x), "=f"(f.y) : "l"(v));
    return f;
}
static __device__ __forceinline__ ull packf2(float x, float y) {
    ull r;
    asm("mov.b64 %0, {%1, %2};" : "=l"(r) : "f"(x), "f"(y));
    return r;
}
static __device__ __forceinline__ ull dupf(float x) {
    ull r;
    asm("mov.b64 %0, {%1, %1};" : "=l"(r) : "f"(x));
    return r;
}
static __device__ __forceinline__ ull h2f2(unsigned int h) {
    __half2 hh = *reinterpret_cast<__half2*>(&h);
    float2 f = __half22float2(hh);
    return packf2(f.x, f.y);
}
static __device__ __forceinline__ void red4(float* p, float4 v) {
    asm volatile("red.global.add.v4.f32 [%0], {%1,%2,%3,%4};"
                 :: "l"(p), "f"(v.x), "f"(v.y), "f"(v.z), "f"(v.w) : "memory");
}

__global__ void k_pad() {}

__global__ void __launch_bounds__(1024) k_init() {
    int idx = blockIdx.x * 1024 + threadIdx.x;   // grid 192 -> 196608
    (&g_sb[0][0])[idx] = 0.0f;
}

// ---------------- fused u_hat generation + iteration-0 s ----------------
// Persistent: grid 296 = 148 n-strips x 2 jk-halves, double-buffered staging.
// Writes u_hat fp16; accumulates s0 = (1/32) sum_n u_hat (fp32) in smem.
__global__ void __launch_bounds__(512, 1) k_uhat(const float* __restrict__ inp,
                                                 const float* __restrict__ W) {
    extern __shared__ float sm[];
    float* S0  = sm;                 // 64b x 512jk (128 KB)
    float* Wb0 = sm + 32768;         // 16i x 512jk
    float* Wb1 = sm + 40960;
    float* Xs0 = sm + 49152;         // 16i x 64b
    float* Xs1 = sm + 50176;         // 200 KB total

    const int tid = threadIdx.x;
    const int jkh = blockIdx.x & 1;
    const int idx = blockIdx.x >> 1;   // 0..147

    for (int t = tid; t < 32768; t += 512) S0[t] = 0.0f;

    const int jkg = jkh * 512 + tid;
    const int wj = jkg >> 5, wk = jkg & 31;
    const float* wbase = W + (size_t)wj * N_ * 512 + wk * 16;
    const int xb = tid >> 3, xi = (tid & 7) * 2;
    const float* xbase = inp + (size_t)xb * N_ * 16 + xi;

    const int jkq = tid & 63;      // jk = jkq*4 (+0..3) and 256+jkq*4
    const int bq  = tid >> 6;      // 8-b group

    const int total = (N_ - idx + 147) / 148;

    float4 wr0, wr1, wr2, wr3; float2 xr;
    {
        const float4* ws = reinterpret_cast<const float4*>(wbase + (size_t)idx * 512);
        wr0 = ws[0]; wr1 = ws[1]; wr2 = ws[2]; wr3 = ws[3];
        xr = *reinterpret_cast<const float2*>(xbase + (size_t)idx * 16);
        Wb0[0*512+tid]=wr0.x;  Wb0[1*512+tid]=wr0.y;  Wb0[2*512+tid]=wr0.z;  Wb0[3*512+tid]=wr0.w;
        Wb0[4*512+tid]=wr1.x;  Wb0[5*512+tid]=wr1.y;  Wb0[6*512+tid]=wr1.z;  Wb0[7*512+tid]=wr1.w;
        Wb0[8*512+tid]=wr2.x;  Wb0[9*512+tid]=wr2.y;  Wb0[10*512+tid]=wr2.z; Wb0[11*512+tid]=wr2.w;
        Wb0[12*512+tid]=wr3.x; Wb0[13*512+tid]=wr3.y; Wb0[14*512+tid]=wr3.z; Wb0[15*512+tid]=wr3.w;
        Xs0[xi * 64 + xb] = xr.x;
        Xs0[(xi + 1) * 64 + xb] = xr.y;
    }

    const ull c2 = dupf(0.03125f);

    for (int t = 0; t < total; t++) {
        __syncthreads();
        const int ncur = idx + t * 148;
        const bool more = (t + 1 < total);
        if (more) {
            const int nn = ncur + 148;
            const float4* ws = reinterpret_cast<const float4*>(wbase + (size_t)nn * 512);
            wr0 = ws[0]; wr1 = ws[1]; wr2 = ws[2]; wr3 = ws[3];
            xr = *reinterpret_cast<const float2*>(xbase + (size_t)nn * 16);
        }
        const float* Wc = (t & 1) ? Wb1 : Wb0;
        const float* Xc = (t & 1) ? Xs1 : Xs0;

        ull acc[8][4];
        #pragma unroll
        for (int m = 0; m < 8; m++)
            #pragma unroll
            for (int p = 0; p < 4; p++) acc[m][p] = 0ull;

        #pragma unroll
        for (int i = 0; i < 16; i++) {
            float4 wa = *reinterpret_cast<const float4*>(Wc + i * 512 + jkq * 4);
            float4 wb = *reinterpret_cast<const float4*>(Wc + i * 512 + 256 + jkq * 4);
            ull wd0 = dupf(wa.x), wd1 = dupf(wa.y), wd2 = dupf(wa.z), wd3 = dupf(wa.w);
            ull wd4 = dupf(wb.x), wd5 = dupf(wb.y), wd6 = dupf(wb.z), wd7 = dupf(wb.w);
            ulonglong2 xu0 = *reinterpret_cast<const ulonglong2*>(Xc + i * 64 + bq * 8);
            ulonglong2 xu1 = *reinterpret_cast<const ulonglong2*>(Xc + i * 64 + bq * 8 + 4);
            ull xp0 = xu0.x, xp1 = xu0.y, xp2 = xu1.x, xp3 = xu1.y;
            acc[0][0]=fma2(wd0,xp0,acc[0][0]); acc[0][1]=fma2(wd0,xp1,acc[0][1]);
            acc[0][2]=fma2(wd0,xp2,acc[0][2]); acc[0][3]=fma2(wd0,xp3,acc[0][3]);
            acc[1][0]=fma2(wd1,xp0,acc[1][0]); acc[1][1]=fma2(wd1,xp1,acc[1][1]);
            acc[1][2]=fma2(wd1,xp2,acc[1][2]); acc[1][3]=fma2(wd1,xp3,acc[1][3]);
            acc[2][0]=fma2(wd2,xp0,acc[2][0]); acc[2][1]=fma2(wd2,xp1,acc[2][1]);
            acc[2][2]=fma2(wd2,xp2,acc[2][2]); acc[2][3]=fma2(wd2,xp3,acc[2][3]);
            acc[3][0]=fma2(wd3,xp0,acc[3][0]); acc[3][1]=fma2(wd3,xp1,acc[3][1]);
            acc[3][2]=fma2(wd3,xp2,acc[3][2]); acc[3][3]=fma2(wd3,xp3,acc[3][3]);
            acc[4][0]=fma2(wd4,xp0,acc[4][0]); acc[4][1]=fma2(wd4,xp1,acc[4][1]);
            acc[4][2]=fma2(wd4,xp2,acc[4][2]); acc[4][3]=fma2(wd4,xp3,acc[4][3]);
            acc[5][0]=fma2(wd5,xp0,acc[5][0]); acc[5][1]=fma2(wd5,xp1,acc[5][1]);
            acc[5][2]=fma2(wd5,xp2,acc[5][2]); acc[5][3]=fma2(wd5,xp3,acc[5][3]);
            acc[6][0]=fma2(wd6,xp0,acc[6][0]); acc[6][1]=fma2(wd6,xp1,acc[6][1]);
            acc[6][2]=fma2(wd6,xp2,acc[6][2]); acc[6][3]=fma2(wd6,xp3,acc[6][3]);
            acc[7][0]=fma2(wd7,xp0,acc[7][0]); acc[7][1]=fma2(wd7,xp1,acc[7][1]);
            acc[7][2]=fma2(wd7,xp2,acc[7][2]); acc[7][3]=fma2(wd7,xp3,acc[7][3]);
        }

        if (more) {
            float* Wn = (t & 1) ? Wb0 : Wb1;
            float* Xn = (t & 1) ? Xs0 : Xs1;
            Wn[0*512+tid]=wr0.x;  Wn[1*512+tid]=wr0.y;  Wn[2*512+tid]=wr0.z;  Wn[3*512+tid]=wr0.w;
            Wn[4*512+tid]=wr1.x;  Wn[5*512+tid]=wr1.y;  Wn[6*512+tid]=wr1.z;  Wn[7*512+tid]=wr1.w;
            Wn[8*512+tid]=wr2.x;  Wn[9*512+tid]=wr2.y;  Wn[10*512+tid]=wr2.z; Wn[11*512+tid]=wr2.w;
            Wn[12*512+tid]=wr3.x; Wn[13*512+tid]=wr3.y; Wn[14*512+tid]=wr3.z; Wn[15*512+tid]=wr3.w;
            Xn[xi * 64 + xb] = xr.x;
            Xn[(xi + 1) * 64 + xb] = xr.y;
        }

        #pragma unroll
        for (int p = 0; p < 4; p++) {
            float2 a0 = ull2f2(acc[0][p]), a1 = ull2f2(acc[1][p]);
            float2 a2 = ull2f2(acc[2][p]), a3 = ull2f2(acc[3][p]);
            float2 a4 = ull2f2(acc[4][p]), a5 = ull2f2(acc[5][p]);
            float2 a6 = ull2f2(acc[6][p]), a7 = ull2f2(acc[7][p]);
            #pragma unroll
            for (int e = 0; e < 2; e++) {
                const int bg = bq * 8 + 2 * p + e;
                float f0 = e ? a0.y : a0.x, f1 = e ? a1.y : a1.x;
                float f2 = e ? a2.y : a2.x, f3 = e ? a3.y : a3.x;
                float f4 = e ? a4.y : a4.x, f5 = e ? a5.y : a5.x;
                float f6 = e ? a6.y : a6.x, f7 = e ? a7.y : a7.x;

                float* sA = S0 + bg * 512 + jkq * 4;
                ulonglong2 oA = *reinterpret_cast<ulonglong2*>(sA);
                oA.x = fma2(packf2(f0, f1), c2, oA.x);
                oA.y = fma2(packf2(f2, f3), c2, oA.y);
                *reinterpret_cast<ulonglong2*>(sA) = oA;
                float* sB = S0 + bg * 512 + 256 + jkq * 4;
                ulonglong2 oB = *reinterpret_cast<ulonglong2*>(sB);
                oB.x = fma2(packf2(f4, f5), c2, oB.x);
                oB.y = fma2(packf2(f6, f7), c2, oB.y);
                *reinterpret_cast<ulonglong2*>(sB) = oB;

                __half2 hA0 = __floats2half2_rn(f0, f1), hA1 = __floats2half2_rn(f2, f3);
                __half2 hB0 = __floats2half2_rn(f4, f5), hB1 = __floats2half2_rn(f6, f7);
                __half* up = g_uhat + ((size_t)bg * N_ + ncur) * JK_ + jkh * 512;
                uint2 vA, vB;
                vA.x = *reinterpret_cast<unsigned int*>(&hA0);
                vA.y = *reinterpret_cast<unsigned int*>(&hA1);
                vB.x = *reinterpret_cast<unsigned int*>(&hB0);
                vB.y = *reinterpret_cast<unsigned int*>(&hB1);
                *reinterpret_cast<uint2*>(up + jkq * 4) = vA;
                *reinterpret_cast<uint2*>(up + 256 + jkq * 4) = vB;
            }
        }
    }

    __syncthreads();
    for (int t2 = tid; t2 < 8192; t2 += 512) {
        int b = t2 >> 7;
        int c = (t2 & 127) * 4;
        float4 v = *reinterpret_cast<float4*>(S0 + b * 512 + c);
        red4(&g_sb[0][b * JK_ + jkh * 512 + c], v);
    }
}

// ---------------- fused squash + routing pass ----------------
// Buffers selected by INDEX (device-side) — __device__ symbols must not be
// passed as host-side kernel arguments.
__global__ void __launch_bounds__(256, 2)
k_route(int ia, int ib, int io, int two) {
    __shared__ float V_sm[1024];
    __shared__ float ws[8 * 1024];     // per-warp s partials

    const float* sa = g_sb[ia];
    const float* sb = g_sb[ib];
    float* sout = g_sb[io];

    const int chunk = blockIdx.x;      // 0..31
    const int b     = blockIdx.y;      // 0..63
    const int tid   = threadIdx.x;     // 256
    const int warp  = tid >> 5;
    const int lane  = tid & 31;

    // --- build V[j][k] = squash(sa) [+ squash(sb)] (warp w -> rows 4w..4w+3) ---
    #pragma unroll
    for (int r = 0; r < 4; r++) {
        int j = warp * 4 + r;
        float va = sa[b * JK_ + j * 32 + lane];
        float sq = va * va;
        #pragma unroll
        for (int o = 16; o; o >>= 1) sq += __shfl_xor_sync(0xffffffffu, sq, o);
        float val = (sq / ((1.0f + sq) * sqrtf(sq + 1e-7f))) * va;
        if (two) {
            float vb = sb[b * JK_ + j * 32 + lane];
            float sqb = vb * vb;
            #pragma unroll
            for (int o = 16; o; o >>= 1) sqb += __shfl_xor_sync(0xffffffffu, sqb, o);
            val += (sqb / ((1.0f + sqb) * sqrtf(sqb + 1e-7f))) * vb;
        }
        V_sm[j * 32 + lane] = val;
    }
    __syncthreads();

    // lane's V slice: for q, jk = q*256 + lane*8 .. +7  (one j per (q,lane))
    ull vq[4][4];
    #pragma unroll
    for (int q = 0; q < 4; q++) {
        float4 a = *reinterpret_cast<const float4*>(V_sm + q * 256 + lane * 8);
        float4 c = *reinterpret_cast<const float4*>(V_sm + q * 256 + lane * 8 + 4);
        vq[q][0] = packf2(a.x, a.y); vq[q][1] = packf2(a.z, a.w);
        vq[q][2] = packf2(c.x, c.y); vq[q][3] = packf2(c.z, c.w);
    }

    ull sacc[4][4];
    #pragma unroll
    for (int q = 0; q < 4; q++)
        #pragma unroll
        for (int m = 0; m < 4; m++) sacc[q][m] = 0ull;

    const char* row0 = reinterpret_cast<const char*>(
        g_uhat + ((size_t)b * N_ + (size_t)(chunk * 64 + warp * 8)) * JK_) + lane * 16;

    uint4 cur0, cur1, cur2, cur3, nxt0, nxt1, nxt2, nxt3;
    cur0 = *reinterpret_cast<const uint4*>(row0);
    cur1 = *reinterpret_cast<const uint4*>(row0 + 512);
    cur2 = *reinterpret_cast<const uint4*>(row0 + 1024);
    cur3 = *reinterpret_cast<const uint4*>(row0 + 1536);

    #pragma unroll
    for (int t = 0; t < 8; t++) {
        if (t < 7) {
            const char* rn = row0 + (size_t)(t + 1) * 2048;
            nxt0 = *reinterpret_cast<const uint4*>(rn);
            nxt1 = *reinterpret_cast<const uint4*>(rn + 512);
            nxt2 = *reinterpret_cast<const uint4*>(rn + 1024);
            nxt3 = *reinterpret_cast<const uint4*>(rn + 1536);
        }
        uint4 c4[4] = {cur0, cur1, cur2, cur3};
        float e[4];
        #pragma unroll
        for (int q = 0; q < 4; q++) {
            ull u0 = h2f2(c4[q].x), u1 = h2f2(c4[q].y);
            ull u2 = h2f2(c4[q].z), u3 = h2f2(c4[q].w);
            ull d = fma2(u0, vq[q][0], fma2(u1, vq[q][1],
                    fma2(u2, vq[q][2], fma2(u3, vq[q][3], 0ull))));
            float2 df = ull2f2(d);
            float bp = df.x + df.y;
            bp += __shfl_xor_sync(0xffffffffu, bp, 1);
            bp += __shfl_xor_sync(0xffffffffu, bp, 2);
            e[q] = __expf(bp);          // logits bounded; no max needed
        }
        float tot = e[0] + e[1] + e[2] + e[3];
        tot += __shfl_xor_sync(0xffffffffu, tot, 4);
        tot += __shfl_xor_sync(0xffffffffu, tot, 8);
        tot += __shfl_xor_sync(0xffffffffu, tot, 16);
        float inv = __fdividef(1.0f, tot);
        #pragma unroll
        for (int q = 0; q < 4; q++) {
            ull cq2 = dupf(e[q] * inv);
            ull u0 = h2f2(c4[q].x), u1 = h2f2(c4[q].y);
            ull u2 = h2f2(c4[q].z), u3 = h2f2(c4[q].w);
            sacc[q][0] = fma2(cq2, u0, sacc[q][0]);
            sacc[q][1] = fma2(cq2, u1, sacc[q][1]);
            sacc[q][2] = fma2(cq2, u2, sacc[q][2]);
            sacc[q][3] = fma2(cq2, u3, sacc[q][3]);
        }
        if (t < 7) { cur0 = nxt0; cur1 = nxt1; cur2 = nxt2; cur3 = nxt3; }
    }

    // per-warp private store (no atomics)
    #pragma unroll
    for (int q = 0; q < 4; q++) {
        float2 f0 = ull2f2(sacc[q][0]), f1 = ull2f2(sacc[q][1]);
        float2 f2 = ull2f2(sacc[q][2]), f3 = ull2f2(sacc[q][3]);
        float* wp = ws + warp * 1024 + q * 256 + lane * 8;
        *reinterpret_cast<float4*>(wp)     = make_float4(f0.x, f0.y, f1.x, f1.y);
        *reinterpret_cast<float4*>(wp + 4) = make_float4(f2.x, f2.y, f3.x, f3.y);
    }
    __syncthreads();

    // cross-warp tree reduce + global flush
    float4 a = *reinterpret_cast<const float4*>(ws + tid * 4);
    #pragma unroll
    for (int w = 1; w < 8; w++) {
        float4 x = *reinterpret_cast<const float4*>(ws + w * 1024 + tid * 4);
        a.x += x.x; a.y += x.y; a.z += x.z; a.w += x.w;
    }
    red4(sout + b * JK_ + tid * 4, a);
}

// ---------------- final squash ----------------
__global__ void __launch_bounds__(1024) k_squash_final(float* __restrict__ out) {
    const int b   = blockIdx.x;
    const int tid = threadIdx.x;      // warp = j, lane = k
    float sv = g_sb[2][b * JK_ + tid];
    float sq = sv * sv;
    #pragma unroll
    for (int o = 16; o; o >>= 1) sq += __shfl_xor_sync(0xffffffffu, sq, o);
    out[b * JK_ + tid] = (sq / ((1.0f + sq) * sqrtf(sq + 1e-7f))) * sv;
}

extern "C" void kernel_launch(void* const* d_in, const int* in_sizes, int n_in,
                              void* d_out, int out_size) {
    const float* inp = (const float*)d_in[0];   // [64, 2048, 16]
    const float* W   = (const float*)d_in[1];   // [32, 2048, 32, 16]
    float* out = (float*)d_out;                 // [64, 32, 32]

    cudaFuncSetAttribute(k_uhat, cudaFuncAttributeMaxDynamicSharedMemorySize, 204800);

    k_init<<<192, 1024>>>();                    // zero s0,s1,s2
    k_uhat<<<296, 512, 204800>>>(inp, W);       // u_hat + s0
    k_pad<<<1, 32>>>();                         // align ncu capture (#4) on route
    k_route<<<dim3(32, 64), 256>>>(0, 0, 1, 0); // V0 -> s1
    k_route<<<dim3(32, 64), 256>>>(0, 1, 2, 1); // V0+V1 -> s2
    k_squash_final<<<64, 1024>>>(out);
}